// round 6
// baseline (speedup 1.0000x reference)
#include <cuda_runtime.h>
#include <cstdint>

#define T_LEN 65536
#define H 108
#define G4 432
#define NGATE 864       // 432 rows x 2 half-row threads (27 warps) -- R3 layout
#define NTHR 960        // + 1 scalar warp + 2 pointwise warps

// ---------------- device scratch ----------------
__device__ float g_imp[2][T_LEN];
__device__ float g_loss[2];
__device__ float g_part[256];

// ---------------- f32x2 helpers ----------------
__device__ __forceinline__ void fma2(unsigned long long &acc, unsigned long long a, unsigned long long b) {
    asm volatile("fma.rn.f32x2 %0, %1, %2, %0;" : "+l"(acc) : "l"(a), "l"(b));
}
__device__ __forceinline__ unsigned long long pk2(float a, float b) {
    unsigned long long r;
    asm("mov.b64 %0, {%1, %2};" : "=l"(r) : "f"(a), "f"(b));
    return r;
}
__device__ __forceinline__ float2 upk(unsigned long long v) {
    float2 r;
    asm("mov.b64 {%0, %1}, %2;" : "=f"(r.x), "=f"(r.y) : "l"(v));
    return r;
}
__device__ __forceinline__ float tanh_fast(float x) {
    float y;
    asm("tanh.approx.f32 %0, %1;" : "=f"(y) : "f"(x));
    return y;
}
__device__ __forceinline__ float sigmoid_fast(float x) {
    return fmaf(tanh_fast(0.5f * x), 0.5f, 0.5f);
}

// ---------------- main recurrence: one block per direction ----------------
__global__ void __launch_bounds__(NTHR, 1) brits_kernel(
    const float* __restrict__ values,  const float* __restrict__ masks,
    const float* __restrict__ deltas_f, const float* __restrict__ deltas_b,
    const float* __restrict__ f_td_w,  const float* __restrict__ f_td_b,
    const float* __restrict__ f_reg_w, const float* __restrict__ f_reg_b,
    const float* __restrict__ f_W_ih,  const float* __restrict__ f_W_hh,
    const float* __restrict__ f_b_ih,  const float* __restrict__ f_b_hh,
    const float* __restrict__ b_td_w,  const float* __restrict__ b_td_b,
    const float* __restrict__ b_reg_w, const float* __restrict__ b_reg_b,
    const float* __restrict__ b_W_ih,  const float* __restrict__ b_W_hh,
    const float* __restrict__ b_b_ih,  const float* __restrict__ b_b_hh)
{
    const int dir = blockIdx.x;
    const float* td_w  = dir ? b_td_w  : f_td_w;
    const float* td_b  = dir ? b_td_b  : f_td_b;
    const float* reg_w = dir ? b_reg_w : f_reg_w;
    const float* reg_b = dir ? b_reg_b : f_reg_b;
    const float* W_ih  = dir ? b_W_ih  : f_W_ih;
    const float* W_hh  = dir ? b_W_hh  : f_W_hh;
    const float* b_ih  = dir ? b_b_ih  : f_b_ih;
    const float* b_hh  = dir ? b_b_hh  : f_b_hh;
    const float* deltas = dir ? deltas_b : deltas_f;

    __shared__ __align__(16) float s_hd[128];   // decayed hidden; [108..127] = 0 pad
    __shared__ float s_gates[G4];               // gate rows i,f,g,o
    __shared__ float s_scalar[2];               // {x_c, m}

    const int tid  = threadIdx.x;
    const int lane = tid & 31;
    const int wid  = tid >> 5;
    const int row  = tid >> 1;     // gate row (gate threads)
    const int half = tid & 1;      // K-half: 0 -> [0,56), 1 -> [56,112)

    const bool is_gate   = (tid < NGATE);
    const bool is_scalar = (wid == 27);
    const bool is_point  = (wid >= 28);
    const int  pt        = tid - 896;           // 0..63 for pointwise warps

    // ---- gate threads: half-row of W_hh in regs (28 x f32x2) ----
    unsigned long long w[28];
    if (is_gate) {
        const float* rw = W_hh + row * H + half * 56;
        const int nreal = half ? 52 : 56;
        #pragma unroll
        for (int i = 0; i < 28; i++) {
            float a = (2 * i     < nreal) ? rw[2 * i]     : 0.0f;
            float b = (2 * i + 1 < nreal) ? rw[2 * i + 1] : 0.0f;
            w[i] = pk2(a, b);
        }
    } else {
        #pragma unroll
        for (int i = 0; i < 28; i++) w[i] = 0ull;
    }

    // ---- scalar warp: reg_w in registers (constant) ----
    float rw0 = 0.0f, rw1 = 0.0f, rw2 = 0.0f, rw3 = 0.0f, rb = 0.0f;
    if (is_scalar) {
        rw0 = reg_w[lane];
        rw1 = (lane + 32 < H) ? reg_w[lane + 32] : 0.0f;
        rw2 = (lane + 64 < H) ? reg_w[lane + 64] : 0.0f;
        rw3 = (lane + 96 < H) ? reg_w[lane + 96] : 0.0f;
        rb  = reg_b[0];
    }

    // ---- pointwise warps: params for 2 units in registers ----
    // unit u: gates rows u, H+u, 2H+u, 3H+u; params Wih0[g], Wih1[g], bias[g]
    float pA[12], pB[12];           // [g*3 + {wih0,wih1,bias}]
    float tdw0 = 0.0f, tdb0 = 0.0f, tdw1 = 0.0f, tdb1 = 0.0f;
    float c0 = 0.0f, c1 = 0.0f, gam0 = 0.0f, gam1 = 0.0f;
    const bool pact = is_point && (pt < 54);
    const int u0 = pt, u1 = pt + 54;
    if (pact) {
        #pragma unroll
        for (int g = 0; g < 4; g++) {
            int rA = g * H + u0, rB = g * H + u1;
            pA[g * 3 + 0] = W_ih[2 * rA];
            pA[g * 3 + 1] = W_ih[2 * rA + 1];
            pA[g * 3 + 2] = b_ih[rA] + b_hh[rA];
            pB[g * 3 + 0] = W_ih[2 * rB];
            pB[g * 3 + 1] = W_ih[2 * rB + 1];
            pB[g * 3 + 2] = b_ih[rB] + b_hh[rB];
        }
        tdw0 = td_w[u0]; tdb0 = td_b[u0];
        tdw1 = td_w[u1]; tdb1 = td_b[u1];
        // gamma for step 0 (decay of initial h=0; value irrelevant but compute anyway)
        float d0 = deltas[0];
        gam0 = __expf(-fmaxf(fmaf(d0, tdw0, tdb0), 0.0f));
        gam1 = __expf(-fmaxf(fmaf(d0, tdw1, tdb1), 0.0f));
    }

    float loss = 0.0f, lcomp = 0.0f;   // scalar warp lane 0 only

    if (tid < 128) s_hd[tid] = 0.0f;
    __syncthreads();

    const uint32_t hd_base = (uint32_t)__cvta_generic_to_shared(s_hd) + (uint32_t)(half * 224);

    for (int t = 0; t < T_LEN; ++t) {
        const int idx = dir ? (T_LEN - 1 - t) : t;

        if (is_gate) {
            // ---- phase A: half-row matvec (14 x LDS.128, broadcast-friendly) ----
            unsigned long long acc0 = 0ull, acc1 = 0ull;
            #pragma unroll
            for (int i = 0; i < 14; i++) {
                unsigned long long h0, h1;
                asm volatile("ld.shared.v2.u64 {%0, %1}, [%2];"
                             : "=l"(h0), "=l"(h1) : "r"(hd_base + 16u * i));
                fma2(acc0, w[2 * i],     h0);
                fma2(acc1, w[2 * i + 1], h1);
            }
            float2 p0 = upk(acc0), p1 = upk(acc1);
            float s = (p0.x + p0.y) + (p1.x + p1.y);
            float tot = s + __shfl_xor_sync(0xffffffffu, s, 1);
            if (half == 0) s_gates[row] = tot;
        } else if (is_scalar) {
            // ---- scalar warp: x_h dot + loss + imputation ----
            float p = rw0 * s_hd[lane] + rw1 * s_hd[lane + 32]
                    + rw2 * s_hd[lane + 64] + rw3 * s_hd[lane + 96];
            #pragma unroll
            for (int o = 16; o > 0; o >>= 1) p += __shfl_xor_sync(0xffffffffu, p, o);
            if (lane == 0) {
                float xv = values[idx], m = masks[idx];
                float x_h = p + rb;
                float x_c = m * xv + (1.0f - m) * x_h;
                float term = fabsf(xv - x_h) * m / (m + 1e-5f);
                float y = term - lcomp;
                float ts = loss + y;
                lcomp = (ts - loss) - y;
                loss = ts;
                g_imp[dir][idx] = x_c;
                s_scalar[0] = x_c;
                s_scalar[1] = m;
            }
        } else if (pact) {
            // ---- pointwise warps during phase A: next-step gamma (hidden work) ----
            int tn = (t + 1 < T_LEN) ? (t + 1) : (T_LEN - 1);
            float dn = deltas[tn];
            gam0 = __expf(-fmaxf(fmaf(dn, tdw0, tdb0), 0.0f));
            gam1 = __expf(-fmaxf(fmaf(dn, tdw1, tdb1), 0.0f));
        }
        __syncthreads();

        // ---- phase B: pointwise LSTM on dedicated warps (params in regs) ----
        if (pact) {
            float xc = s_scalar[0], m = s_scalar[1];
            // unit u0
            float gi0 = fmaf(pA[0], xc, fmaf(pA[1],  m, s_gates[u0]          + pA[2]));
            float gf0 = fmaf(pA[3], xc, fmaf(pA[4],  m, s_gates[H + u0]      + pA[5]));
            float gg0 = fmaf(pA[6], xc, fmaf(pA[7],  m, s_gates[2 * H + u0]  + pA[8]));
            float go0 = fmaf(pA[9], xc, fmaf(pA[10], m, s_gates[3 * H + u0]  + pA[11]));
            // unit u1
            float gi1 = fmaf(pB[0], xc, fmaf(pB[1],  m, s_gates[u1]          + pB[2]));
            float gf1 = fmaf(pB[3], xc, fmaf(pB[4],  m, s_gates[H + u1]      + pB[5]));
            float gg1 = fmaf(pB[6], xc, fmaf(pB[7],  m, s_gates[2 * H + u1]  + pB[8]));
            float go1 = fmaf(pB[9], xc, fmaf(pB[10], m, s_gates[3 * H + u1]  + pB[11]));

            float si0 = sigmoid_fast(gi0), sf0 = sigmoid_fast(gf0), so0 = sigmoid_fast(go0);
            float tg0 = tanh_fast(gg0);
            float si1 = sigmoid_fast(gi1), sf1 = sigmoid_fast(gf1), so1 = sigmoid_fast(go1);
            float tg1 = tanh_fast(gg1);

            c0 = sf0 * c0 + si0 * tg0;
            c1 = sf1 * c1 + si1 * tg1;
            float h0 = so0 * tanh_fast(c0);
            float h1 = so1 * tanh_fast(c1);
            s_hd[u0] = h0 * gam0;       // decay for t+1 folded in
            s_hd[u1] = h1 * gam1;
        }
        __syncthreads();
    }

    if (is_scalar && lane == 0) g_loss[dir] = loss;
}

// ---------------- combine + finalize ----------------
__global__ void combine_kernel(float* __restrict__ out)
{
    __shared__ float red[256];
    const int i = blockIdx.x * 256 + threadIdx.x;
    float a = g_imp[0][i];
    float b = g_imp[1][i];
    out[1 + i] = 0.5f * (a + b);
    red[threadIdx.x] = fabsf(a - b);
    __syncthreads();
    #pragma unroll
    for (int s = 128; s > 0; s >>= 1) {
        if (threadIdx.x < s) red[threadIdx.x] += red[threadIdx.x + s];
        __syncthreads();
    }
    if (threadIdx.x == 0) g_part[blockIdx.x] = red[0];
}

__global__ void finalize_kernel(float* __restrict__ out)
{
    __shared__ float red[256];
    red[threadIdx.x] = g_part[threadIdx.x];
    __syncthreads();
    #pragma unroll
    for (int s = 128; s > 0; s >>= 1) {
        if (threadIdx.x < s) red[threadIdx.x] += red[threadIdx.x + s];
        __syncthreads();
    }
    if (threadIdx.x == 0) {
        float loss_c = red[0] / (float)T_LEN;
        out[0] = 0.3f * (g_loss[0] + g_loss[1]) + loss_c;
    }
}

// ---------------- launch ----------------
extern "C" void kernel_launch(void* const* d_in, const int* in_sizes, int n_in,
                              void* d_out, int out_size)
{
    (void)in_sizes; (void)n_in; (void)out_size;
    const float* values   = (const float*)d_in[0];
    const float* masks    = (const float*)d_in[1];
    const float* deltas_f = (const float*)d_in[2];
    const float* deltas_b = (const float*)d_in[3];
    const float* f_td_w   = (const float*)d_in[4];
    const float* f_td_b   = (const float*)d_in[5];
    const float* f_reg_w  = (const float*)d_in[6];
    const float* f_reg_b  = (const float*)d_in[7];
    const float* f_W_ih   = (const float*)d_in[8];
    const float* f_W_hh   = (const float*)d_in[9];
    const float* f_b_ih   = (const float*)d_in[10];
    const float* f_b_hh   = (const float*)d_in[11];
    const float* b_td_w   = (const float*)d_in[12];
    const float* b_td_b   = (const float*)d_in[13];
    const float* b_reg_w  = (const float*)d_in[14];
    const float* b_reg_b  = (const float*)d_in[15];
    const float* b_W_ih   = (const float*)d_in[16];
    const float* b_W_hh   = (const float*)d_in[17];
    const float* b_b_ih   = (const float*)d_in[18];
    const float* b_b_hh   = (const float*)d_in[19];
    float* out = (float*)d_out;

    brits_kernel<<<2, NTHR>>>(values, masks, deltas_f, deltas_b,
                              f_td_w, f_td_b, f_reg_w, f_reg_b, f_W_ih, f_W_hh, f_b_ih, f_b_hh,
                              b_td_w, b_td_b, b_reg_w, b_reg_b, b_W_ih, b_W_hh, b_b_ih, b_b_hh);
    combine_kernel<<<T_LEN / 256, 256>>>(out);
    finalize_kernel<<<1, 256>>>(out);
}

// round 7
// speedup vs baseline: 1.2160x; 1.2160x over previous
#include <cuda_runtime.h>
#include <cstdint>

#define T_LEN 65536
#define H 108
#define G4 432
#define NTHR 896        // 27 gate warps (each owns 4 units end-to-end) + 1 scalar warp

// ---------------- device scratch ----------------
__device__ float g_imp[2][T_LEN];
__device__ float g_loss[2];
__device__ float g_part[256];

// ---------------- f32x2 helpers ----------------
__device__ __forceinline__ void fma2(unsigned long long &acc, unsigned long long a, unsigned long long b) {
    asm volatile("fma.rn.f32x2 %0, %1, %2, %0;" : "+l"(acc) : "l"(a), "l"(b));
}
__device__ __forceinline__ unsigned long long pk2(float a, float b) {
    unsigned long long r;
    asm("mov.b64 %0, {%1, %2};" : "=l"(r) : "f"(a), "f"(b));
    return r;
}
__device__ __forceinline__ float2 upk(unsigned long long v) {
    float2 r;
    asm("mov.b64 {%0, %1}, %2;" : "=f"(r.x), "=f"(r.y) : "l"(v));
    return r;
}
__device__ __forceinline__ float tanh_fast(float x) {
    float y;
    asm("tanh.approx.f32 %0, %1;" : "=f"(y) : "f"(x));
    return y;
}
__device__ __forceinline__ float sigmoid_fast(float x) {
    return fmaf(tanh_fast(0.5f * x), 0.5f, 0.5f);
}

// ---------------- main recurrence: one block per direction ----------------
__global__ void __launch_bounds__(NTHR, 1) brits_kernel(
    const float* __restrict__ values,  const float* __restrict__ masks,
    const float* __restrict__ deltas_f, const float* __restrict__ deltas_b,
    const float* __restrict__ f_td_w,  const float* __restrict__ f_td_b,
    const float* __restrict__ f_reg_w, const float* __restrict__ f_reg_b,
    const float* __restrict__ f_W_ih,  const float* __restrict__ f_W_hh,
    const float* __restrict__ f_b_ih,  const float* __restrict__ f_b_hh,
    const float* __restrict__ b_td_w,  const float* __restrict__ b_td_b,
    const float* __restrict__ b_reg_w, const float* __restrict__ b_reg_b,
    const float* __restrict__ b_W_ih,  const float* __restrict__ b_W_hh,
    const float* __restrict__ b_b_ih,  const float* __restrict__ b_b_hh)
{
    const int dir = blockIdx.x;
    const float* td_w  = dir ? b_td_w  : f_td_w;
    const float* td_b  = dir ? b_td_b  : f_td_b;
    const float* reg_w = dir ? b_reg_w : f_reg_w;
    const float* reg_b = dir ? b_reg_b : f_reg_b;
    const float* W_ih  = dir ? b_W_ih  : f_W_ih;
    const float* W_hh  = dir ? b_W_hh  : f_W_hh;
    const float* b_ih  = dir ? b_b_ih  : f_b_ih;
    const float* b_hh  = dir ? b_b_hh  : f_b_hh;
    const float* deltas = dir ? deltas_b : deltas_f;

    // double-buffered decayed hidden state; [108..127] of each buffer = 0 pad
    __shared__ __align__(16) float s_hd[2][128];
    // per-gate-row params: {W_ih[:,0], W_ih[:,1], b_ih+b_hh, aux}; aux(q=0)=td_w[u], aux(q=1)=td_b[u]
    __shared__ __align__(16) float s_pw[G4][4];
    __shared__ float s_scalar[2];               // {x_c, m} for current step
    __shared__ unsigned int s_flag;             // monotonic step counter (release/acquire)

    const int tid  = threadIdx.x;
    const int lane = tid & 31;
    const int wid  = tid >> 5;
    const bool is_scalar = (wid == 27);

    // gate-lane decode: lane = v*8 + q*2 + half
    const int v    = lane >> 3;
    const int q    = (lane >> 1) & 3;
    const int half = lane & 1;
    const int u    = 4 * wid + v;          // unit owned (gate warps only)

    // ---- weights: W_hh row (q*H+u), K-half in regs (28 x f32x2) ----
    unsigned long long w[28];
    if (!is_scalar) {
        const float* rw = W_hh + (q * H + u) * H;
        const int k0 = half * 56;
        #pragma unroll
        for (int i = 0; i < 28; i++) {
            int k = k0 + 2 * i;
            float a = (k     < H) ? rw[k]     : 0.0f;
            float b = (k + 1 < H) ? rw[k + 1] : 0.0f;
            w[i] = pk2(a, b);
        }
    } else {
        #pragma unroll
        for (int i = 0; i < 28; i++) w[i] = 0ull;
    }

    // ---- pointwise param table ----
    for (int k2 = tid; k2 < G4; k2 += NTHR) {
        int qq = k2 / H, uu = k2 % H;
        float aux = (qq == 0) ? td_w[uu] : (qq == 1) ? td_b[uu] : 0.0f;
        float4 pv;
        pv.x = W_ih[2 * k2];
        pv.y = W_ih[2 * k2 + 1];
        pv.z = b_ih[k2] + b_hh[k2];
        pv.w = aux;
        *(float4*)&s_pw[k2][0] = pv;
    }

    // ---- scalar warp constants ----
    float4 rwv = make_float4(0.f, 0.f, 0.f, 0.f);
    float rb = 0.0f;
    if (is_scalar) {
        if (lane < 27) rwv = *(const float4*)&reg_w[lane * 4];
        rb = reg_b[0];
    }

    float c_state = 0.0f;                   // cell state (pointwise lanes)
    float loss = 0.0f, lcomp = 0.0f;        // Kahan (scalar lane 0)

    if (tid < 256) ((float*)s_hd)[tid] = 0.0f;
    if (tid == 0) s_flag = 0u;
    __syncthreads();

    const uint32_t hd_smem  = (uint32_t)__cvta_generic_to_shared(&s_hd[0][0]);
    const uint32_t flag_ad  = (uint32_t)__cvta_generic_to_shared(&s_flag);

    for (int t = 0; t < T_LEN; ++t) {
        const int idx = dir ? (T_LEN - 1 - t) : t;
        const int cb  = t & 1;              // current h buffer

        if (!is_scalar) {
            // prefetch next-step delta (broadcast LDG; consumed late in pointwise)
            int tn = (t + 1 < T_LEN) ? (t + 1) : (T_LEN - 1);
            float dn = deltas[tn];

            // ---- matvec: 14 x LDS.128 (2 distinct addrs/warp -> broadcast) ----
            const uint32_t ca = hd_smem + ((uint32_t)cb << 9) + (uint32_t)(half * 224);
            unsigned long long acc0 = 0ull, acc1 = 0ull;
            #pragma unroll
            for (int i = 0; i < 14; i++) {
                unsigned long long h0, h1;
                asm volatile("ld.shared.v2.u64 {%0, %1}, [%2];"
                             : "=l"(h0), "=l"(h1) : "r"(ca + 16u * i));
                fma2(acc0, w[2 * i],     h0);
                fma2(acc1, w[2 * i + 1], h1);
            }
            float2 p0 = upk(acc0), p1 = upk(acc1);
            float s = (p0.x + p0.y) + (p1.x + p1.y);
            // combine K-halves: lanes 2r,2r+1 -> row sum r
            s += __shfl_xor_sync(0xffffffffu, s, 1);
            // gather 4 gate sums onto every lane of the v-group
            const int base = lane & 24;
            float si_ = __shfl_sync(0xffffffffu, s, base);
            float sf_ = __shfl_sync(0xffffffffu, s, base + 2);
            float sg_ = __shfl_sync(0xffffffffu, s, base + 4);
            float so_ = __shfl_sync(0xffffffffu, s, base + 6);

            if ((lane & 7) == 0) {
                // wait for scalar warp's x_c of this step (fast path: already set)
                unsigned int fv;
                do {
                    asm volatile("ld.acquire.cta.shared.u32 %0, [%1];"
                                 : "=r"(fv) : "r"(flag_ad) : "memory");
                } while (fv <= (unsigned int)t);
                float xc = s_scalar[0];
                float m  = s_scalar[1];

                float4 P0 = *(const float4*)&s_pw[u][0];
                float4 P1 = *(const float4*)&s_pw[H + u][0];
                float4 P2 = *(const float4*)&s_pw[2 * H + u][0];
                float4 P3 = *(const float4*)&s_pw[3 * H + u][0];

                float gi = fmaf(P0.x, xc, fmaf(P0.y, m, si_ + P0.z));
                float gf = fmaf(P1.x, xc, fmaf(P1.y, m, sf_ + P1.z));
                float gg = fmaf(P2.x, xc, fmaf(P2.y, m, sg_ + P2.z));
                float go = fmaf(P3.x, xc, fmaf(P3.y, m, so_ + P3.z));

                float ii = sigmoid_fast(gi);
                float ff = sigmoid_fast(gf);
                float oo = sigmoid_fast(go);
                float tg = tanh_fast(gg);
                c_state = ff * c_state + ii * tg;
                float hh = oo * tanh_fast(c_state);

                // next-step decay folded into the store (tdw=P0.w, tdb=P1.w)
                float gam = __expf(-fmaxf(fmaf(dn, P0.w, P1.w), 0.0f));
                s_hd[cb ^ 1][u] = hh * gam;
            }
        } else {
            // ---- scalar warp: x_h dot + loss + imputation + x_c publish ----
            float xv = values[idx];
            float m  = masks[idx];
            float p = 0.0f;
            if (lane < 27) {
                float4 hv = *(const float4*)&s_hd[cb][lane * 4];
                p = rwv.x * hv.x + rwv.y * hv.y + rwv.z * hv.z + rwv.w * hv.w;
            }
            #pragma unroll
            for (int o = 16; o > 0; o >>= 1) p += __shfl_xor_sync(0xffffffffu, p, o);
            if (lane == 0) {
                float x_h = p + rb;
                float x_c = m * xv + (1.0f - m) * x_h;
                float term = fabsf(xv - x_h) * m / (m + 1e-5f);
                float y = term - lcomp;
                float ts = loss + y;
                lcomp = (ts - loss) - y;
                loss = ts;
                g_imp[dir][idx] = x_c;
                s_scalar[0] = x_c;
                s_scalar[1] = m;
                unsigned int nf = (unsigned int)(t + 1);
                asm volatile("st.release.cta.shared.u32 [%0], %1;"
                             :: "r"(flag_ad), "r"(nf) : "memory");
            }
        }
        __syncthreads();
    }

    if (is_scalar && lane == 0) g_loss[dir] = loss;
}

// ---------------- combine + finalize ----------------
__global__ void combine_kernel(float* __restrict__ out)
{
    __shared__ float red[256];
    const int i = blockIdx.x * 256 + threadIdx.x;
    float a = g_imp[0][i];
    float b = g_imp[1][i];
    out[1 + i] = 0.5f * (a + b);
    red[threadIdx.x] = fabsf(a - b);
    __syncthreads();
    #pragma unroll
    for (int s = 128; s > 0; s >>= 1) {
        if (threadIdx.x < s) red[threadIdx.x] += red[threadIdx.x + s];
        __syncthreads();
    }
    if (threadIdx.x == 0) g_part[blockIdx.x] = red[0];
}

__global__ void finalize_kernel(float* __restrict__ out)
{
    __shared__ float red[256];
    red[threadIdx.x] = g_part[threadIdx.x];
    __syncthreads();
    #pragma unroll
    for (int s = 128; s > 0; s >>= 1) {
        if (threadIdx.x < s) red[threadIdx.x] += red[threadIdx.x + s];
        __syncthreads();
    }
    if (threadIdx.x == 0) {
        float loss_c = red[0] / (float)T_LEN;
        out[0] = 0.3f * (g_loss[0] + g_loss[1]) + loss_c;
    }
}

// ---------------- launch ----------------
extern "C" void kernel_launch(void* const* d_in, const int* in_sizes, int n_in,
                              void* d_out, int out_size)
{
    (void)in_sizes; (void)n_in; (void)out_size;
    const float* values   = (const float*)d_in[0];
    const float* masks    = (const float*)d_in[1];
    const float* deltas_f = (const float*)d_in[2];
    const float* deltas_b = (const float*)d_in[3];
    const float* f_td_w   = (const float*)d_in[4];
    const float* f_td_b   = (const float*)d_in[5];
    const float* f_reg_w  = (const float*)d_in[6];
    const float* f_reg_b  = (const float*)d_in[7];
    const float* f_W_ih   = (const float*)d_in[8];
    const float* f_W_hh   = (const float*)d_in[9];
    const float* f_b_ih   = (const float*)d_in[10];
    const float* f_b_hh   = (const float*)d_in[11];
    const float* b_td_w   = (const float*)d_in[12];
    const float* b_td_b   = (const float*)d_in[13];
    const float* b_reg_w  = (const float*)d_in[14];
    const float* b_reg_b  = (const float*)d_in[15];
    const float* b_W_ih   = (const float*)d_in[16];
    const float* b_W_hh   = (const float*)d_in[17];
    const float* b_b_ih   = (const float*)d_in[18];
    const float* b_b_hh   = (const float*)d_in[19];
    float* out = (float*)d_out;

    brits_kernel<<<2, NTHR>>>(values, masks, deltas_f, deltas_b,
                              f_td_w, f_td_b, f_reg_w, f_reg_b, f_W_ih, f_W_hh, f_b_ih, f_b_hh,
                              b_td_w, b_td_b, b_reg_w, b_reg_b, b_W_ih, b_W_hh, b_b_ih, b_b_hh);
    combine_kernel<<<T_LEN / 256, 256>>>(out);
    finalize_kernel<<<1, 256>>>(out);
}

// round 9
// speedup vs baseline: 1.2840x; 1.0560x over previous
#include <cuda_runtime.h>
#include <cstdint>

#define T_LEN 65536
#define H 108
#define G4 432
#define NGATE 864       // 432 rows x 2 half-row threads (27 warps) -- R3 layout
#define NTHR 896        // + 1 scalar warp

// ---------------- device scratch (static) ----------------
__device__ float g_imp[2][T_LEN];
__device__ float g_loss[2];
__device__ float g_part[256];
__device__ float g_gamma[2][T_LEN][H];   // precomputed temporal-decay factors

// ---------------- f32x2 helpers ----------------
__device__ __forceinline__ void fma2(unsigned long long &acc, unsigned long long a, unsigned long long b) {
    asm volatile("fma.rn.f32x2 %0, %1, %2, %0;" : "+l"(acc) : "l"(a), "l"(b));
}
__device__ __forceinline__ unsigned long long pk2(float a, float b) {
    unsigned long long r;
    asm("mov.b64 %0, {%1, %2};" : "=l"(r) : "f"(a), "f"(b));
    return r;
}
__device__ __forceinline__ float2 upk(unsigned long long v) {
    float2 r;
    asm("mov.b64 {%0, %1}, %2;" : "=f"(r.x), "=f"(r.y) : "l"(v));
    return r;
}
__device__ __forceinline__ float tanh_fast(float x) {
    float y;
    asm("tanh.approx.f32 %0, %1;" : "=f"(y) : "f"(x));
    return y;
}
__device__ __forceinline__ float sigmoid_fast(float x) {
    return fmaf(tanh_fast(0.5f * x), 0.5f, 0.5f);
}

// ---------------- gamma precompute: full-chip parallel ----------------
__global__ void gamma_kernel(
    const float* __restrict__ deltas_f, const float* __restrict__ deltas_b,
    const float* __restrict__ f_td_w,  const float* __restrict__ f_td_b,
    const float* __restrict__ b_td_w,  const float* __restrict__ b_td_b)
{
    long long g = (long long)blockIdx.x * 256 + threadIdx.x;   // 2*T_LEN*H total
    int j = (int)(g % H);
    long long rt = g / H;
    int t   = (int)(rt % T_LEN);
    int dir = (int)(rt / T_LEN);
    float d = dir ? deltas_b[t] : deltas_f[t];
    float w = dir ? b_td_w[j]   : f_td_w[j];
    float b = dir ? b_td_b[j]   : f_td_b[j];
    g_gamma[dir][t][j] = __expf(-fmaxf(fmaf(d, w, b), 0.0f));
}

// ---------------- main recurrence: one block per direction ----------------
__global__ void __launch_bounds__(NTHR, 1) brits_kernel(
    const float* __restrict__ values,  const float* __restrict__ masks,
    const float* __restrict__ deltas_f, const float* __restrict__ deltas_b,
    const float* __restrict__ f_td_w,  const float* __restrict__ f_td_b,
    const float* __restrict__ f_reg_w, const float* __restrict__ f_reg_b,
    const float* __restrict__ f_W_ih,  const float* __restrict__ f_W_hh,
    const float* __restrict__ f_b_ih,  const float* __restrict__ f_b_hh,
    const float* __restrict__ b_td_w,  const float* __restrict__ b_td_b,
    const float* __restrict__ b_reg_w, const float* __restrict__ b_reg_b,
    const float* __restrict__ b_W_ih,  const float* __restrict__ b_W_hh,
    const float* __restrict__ b_b_ih,  const float* __restrict__ b_b_hh)
{
    const int dir = blockIdx.x;
    const float* reg_w = dir ? b_reg_w : f_reg_w;
    const float* reg_b = dir ? b_reg_b : f_reg_b;
    const float* W_ih  = dir ? b_W_ih  : f_W_ih;
    const float* W_hh  = dir ? b_W_hh  : f_W_hh;
    const float* b_ih  = dir ? b_b_ih  : f_b_ih;
    const float* b_hh  = dir ? b_b_hh  : f_b_hh;

    __shared__ __align__(16) float s_hd[128];    // decayed hidden; [108..127] = 0 pad
    __shared__ __align__(16) float s_gT[H][4];   // gate sums transposed: [u] = {i,f,g,o}
    __shared__ __align__(16) float s_pp[H][12];  // packed per-unit pointwise params
    __shared__ float s_scalar[2];                // {x_c, m}

    const int tid  = threadIdx.x;
    const int lane = tid & 31;
    const int row  = tid >> 1;     // gate row r = q*H+u  (gate threads)
    const int half = tid & 1;      // K-half: 0 -> [0,56), 1 -> [56,112)
    const bool is_scalar = (tid >= NGATE);

    // ---- gate threads: half-row of W_hh in regs (28 x f32x2) ----
    unsigned long long w[28];
    if (!is_scalar) {
        const float* rw = W_hh + row * H + half * 56;
        const int nreal = half ? 52 : 56;
        #pragma unroll
        for (int i = 0; i < 28; i++) {
            float a = (2 * i     < nreal) ? rw[2 * i]     : 0.0f;
            float b = (2 * i + 1 < nreal) ? rw[2 * i + 1] : 0.0f;
            w[i] = pk2(a, b);
        }
    } else {
        #pragma unroll
        for (int i = 0; i < 28; i++) w[i] = 0ull;
    }

    // ---- packed pointwise params: s_pp[u][3g+{w0,w1,b}] ----
    for (int k = tid; k < 12 * H; k += NTHR) {
        int u = k / 12;
        int slot = k % 12;
        int g = slot / 3;
        int which = slot % 3;
        int r = g * H + u;
        float v;
        if (which == 0)      v = W_ih[2 * r];
        else if (which == 1) v = W_ih[2 * r + 1];
        else                 v = b_ih[r] + b_hh[r];
        s_pp[u][slot] = v;
    }

    // ---- scalar warp constants in regs ----
    float4 rwv = make_float4(0.f, 0.f, 0.f, 0.f);
    float rb = 0.0f;
    if (is_scalar) {
        if (lane < 27) rwv = *(const float4*)&reg_w[lane * 4];
        rb = reg_b[0];
    }

    float c_state = 0.0f;                   // cell state (threads 0..107)
    float loss = 0.0f, lcomp = 0.0f;        // Kahan (scalar warp lane 0)

    if (tid < 128) s_hd[tid] = 0.0f;
    __syncthreads();

    const uint32_t hd_base = (uint32_t)__cvta_generic_to_shared(s_hd) + (uint32_t)(half * 224);

    for (int t = 0; t < T_LEN; ++t) {
        const int idx = dir ? (T_LEN - 1 - t) : t;

        // prefetch next-step gamma (hidden behind phase A; used in phase B)
        float gam = 0.0f;
        if (tid < H) {
            int tn = (t + 1 < T_LEN) ? (t + 1) : (T_LEN - 1);
            gam = g_gamma[dir][tn][tid];
        }

        if (!is_scalar) {
            // ---- phase A: half-row matvec (14 x LDS.128, broadcast-friendly) ----
            unsigned long long acc0 = 0ull, acc1 = 0ull;
            #pragma unroll
            for (int i = 0; i < 14; i++) {
                unsigned long long h0, h1;
                asm volatile("ld.shared.v2.u64 {%0, %1}, [%2];"
                             : "=l"(h0), "=l"(h1) : "r"(hd_base + 16u * i));
                fma2(acc0, w[2 * i],     h0);
                fma2(acc1, w[2 * i + 1], h1);
            }
            float2 p0 = upk(acc0), p1 = upk(acc1);
            float s = (p0.x + p0.y) + (p1.x + p1.y);
            float tot = s + __shfl_xor_sync(0xffffffffu, s, 1);
            if (half == 0) {
                int q = row / H, u = row % H;
                s_gT[u][q] = tot;           // transposed store
            }
        } else {
            // ---- scalar warp: x_h dot + loss + imputation ----
            float p = 0.0f;
            if (lane < 27) {
                float4 hv = *(const float4*)&s_hd[lane * 4];
                p = rwv.x * hv.x + rwv.y * hv.y + rwv.z * hv.z + rwv.w * hv.w;
            }
            #pragma unroll
            for (int o = 16; o > 0; o >>= 1) p += __shfl_xor_sync(0xffffffffu, p, o);
            if (lane == 0) {
                float xv = values[idx], m = masks[idx];
                float x_h = p + rb;
                float x_c = m * xv + (1.0f - m) * x_h;
                float term = fabsf(xv - x_h) * m / (m + 1e-5f);
                float y = term - lcomp;
                float ts = loss + y;
                lcomp = (ts - loss) - y;
                loss = ts;
                g_imp[dir][idx] = x_c;
                s_scalar[0] = x_c;
                s_scalar[1] = m;
            }
        }
        __syncthreads();

        // ---- phase B: pointwise LSTM cell (threads 0..107) ----
        if (tid < H) {
            const int u = tid;
            float4 gv = *(const float4*)&s_gT[u][0];      // {i,f,g,o} matvec sums
            const float* pp = &s_pp[u][0];
            float4 a0 = *(const float4*)(pp);             // iw0,iw1,ib, fw0
            float4 a1 = *(const float4*)(pp + 4);         // fw1,fb, gw0,gw1
            float4 a2 = *(const float4*)(pp + 8);         // gb, ow0,ow1,ob
            float xc = s_scalar[0], m = s_scalar[1];

            float gi = fmaf(a0.x, xc, fmaf(a0.y, m, gv.x + a0.z));
            float gf = fmaf(a0.w, xc, fmaf(a1.x, m, gv.y + a1.y));
            float gg = fmaf(a1.z, xc, fmaf(a1.w, m, gv.z + a2.x));
            float go = fmaf(a2.y, xc, fmaf(a2.z, m, gv.w + a2.w));

            float si = sigmoid_fast(gi);
            float sf = sigmoid_fast(gf);
            float so = sigmoid_fast(go);
            float tg = tanh_fast(gg);
            c_state = sf * c_state + si * tg;
            float hh = so * tanh_fast(c_state);
            s_hd[u] = hh * gam;             // next-step decay folded in (prefetched)
        }
        __syncthreads();
    }

    if (is_scalar && lane == 0) g_loss[dir] = loss;
}

// ---------------- combine + finalize ----------------
__global__ void combine_kernel(float* __restrict__ out)
{
    __shared__ float red[256];
    const int i = blockIdx.x * 256 + threadIdx.x;
    float a = g_imp[0][i];
    float b = g_imp[1][i];
    out[1 + i] = 0.5f * (a + b);
    red[threadIdx.x] = fabsf(a - b);
    __syncthreads();
    #pragma unroll
    for (int s = 128; s > 0; s >>= 1) {
        if (threadIdx.x < s) red[threadIdx.x] += red[threadIdx.x + s];
        __syncthreads();
    }
    if (threadIdx.x == 0) g_part[blockIdx.x] = red[0];
}

__global__ void finalize_kernel(float* __restrict__ out)
{
    __shared__ float red[256];
    red[threadIdx.x] = g_part[threadIdx.x];
    __syncthreads();
    #pragma unroll
    for (int s = 128; s > 0; s >>= 1) {
        if (threadIdx.x < s) red[threadIdx.x] += red[threadIdx.x + s];
        __syncthreads();
    }
    if (threadIdx.x == 0) {
        float loss_c = red[0] / (float)T_LEN;
        out[0] = 0.3f * (g_loss[0] + g_loss[1]) + loss_c;
    }
}

// ---------------- launch ----------------
extern "C" void kernel_launch(void* const* d_in, const int* in_sizes, int n_in,
                              void* d_out, int out_size)
{
    (void)in_sizes; (void)n_in; (void)out_size;
    const float* values   = (const float*)d_in[0];
    const float* masks    = (const float*)d_in[1];
    const float* deltas_f = (const float*)d_in[2];
    const float* deltas_b = (const float*)d_in[3];
    const float* f_td_w   = (const float*)d_in[4];
    const float* f_td_b   = (const float*)d_in[5];
    const float* f_reg_w  = (const float*)d_in[6];
    const float* f_reg_b  = (const float*)d_in[7];
    const float* f_W_ih   = (const float*)d_in[8];
    const float* f_W_hh   = (const float*)d_in[9];
    const float* f_b_ih   = (const float*)d_in[10];
    const float* f_b_hh   = (const float*)d_in[11];
    const float* b_td_w   = (const float*)d_in[12];
    const float* b_td_b   = (const float*)d_in[13];
    const float* b_reg_w  = (const float*)d_in[14];
    const float* b_reg_b  = (const float*)d_in[15];
    const float* b_W_ih   = (const float*)d_in[16];
    const float* b_W_hh   = (const float*)d_in[17];
    const float* b_b_ih   = (const float*)d_in[18];
    const float* b_b_hh   = (const float*)d_in[19];
    float* out = (float*)d_out;

    // 2*T_LEN*H / 256 = 55,296 blocks exactly
    gamma_kernel<<<(2 * T_LEN * H) / 256, 256>>>(deltas_f, deltas_b,
                                                 f_td_w, f_td_b, b_td_w, b_td_b);
    brits_kernel<<<2, NTHR>>>(values, masks, deltas_f, deltas_b,
                              f_td_w, f_td_b, f_reg_w, f_reg_b, f_W_ih, f_W_hh, f_b_ih, f_b_hh,
                              b_td_w, b_td_b, b_reg_w, b_reg_b, b_W_ih, b_W_hh, b_b_ih, b_b_hh);
    combine_kernel<<<T_LEN / 256, 256>>>(out);
    finalize_kernel<<<1, 256>>>(out);
}

// round 10
// speedup vs baseline: 1.6130x; 1.2562x over previous
#include <cuda_runtime.h>
#include <cstdint>

#define T_LEN 65536
#define H 108
#define G4 432          // 4*H gate rows
#define NGATE 864       // 432 rows x 2 half-row threads (27 warps)
#define NTHR 896        // + 1 scalar warp

// ---------------- device scratch (static: no allocation allowed) ----------------
__device__ float g_imp[2][T_LEN];   // per-direction imputations (forward time order)
__device__ float g_loss[2];
__device__ float g_part[256];

// ---------------- activation helpers ----------------
__device__ __forceinline__ float tanh_fast(float x) {
    float y;
    asm("tanh.approx.f32 %0, %1;" : "=f"(y) : "f"(x));
    return y;
}
__device__ __forceinline__ float sigmoid_fast(float x) {
    return fmaf(tanh_fast(0.5f * x), 0.5f, 0.5f);
}

// ---------------- main recurrence: one block per direction ----------------
__global__ void __launch_bounds__(NTHR, 1) brits_kernel(
    const float* __restrict__ values,  const float* __restrict__ masks,
    const float* __restrict__ deltas_f, const float* __restrict__ deltas_b,
    const float* __restrict__ f_td_w,  const float* __restrict__ f_td_b,
    const float* __restrict__ f_reg_w, const float* __restrict__ f_reg_b,
    const float* __restrict__ f_W_ih,  const float* __restrict__ f_W_hh,
    const float* __restrict__ f_b_ih,  const float* __restrict__ f_b_hh,
    const float* __restrict__ b_td_w,  const float* __restrict__ b_td_b,
    const float* __restrict__ b_reg_w, const float* __restrict__ b_reg_b,
    const float* __restrict__ b_W_ih,  const float* __restrict__ b_W_hh,
    const float* __restrict__ b_b_ih,  const float* __restrict__ b_b_hh)
{
    const int dir = blockIdx.x;
    const float* td_w  = dir ? b_td_w  : f_td_w;
    const float* td_b  = dir ? b_td_b  : f_td_b;
    const float* reg_w = dir ? b_reg_w : f_reg_w;
    const float* reg_b = dir ? b_reg_b : f_reg_b;
    const float* W_ih  = dir ? b_W_ih  : f_W_ih;
    const float* W_hh  = dir ? b_W_hh  : f_W_hh;
    const float* b_ih  = dir ? b_b_ih  : f_b_ih;
    const float* b_hh  = dir ? b_b_hh  : f_b_hh;
    const float* deltas = dir ? deltas_b : deltas_f;

    __shared__ __align__(16) float s_hd[128];   // decayed hidden; [108..127] = 0 pad
    __shared__ float s_gates[G4];               // W_hh @ h_decayed per gate row
    __shared__ float s_scalar[2];               // {x_c, m} for current step
    __shared__ float s_par[12][H];              // input weights / fused biases, SoA
    __shared__ float s_c[H];                    // cell state (smem to spare regs)
    __shared__ float s_tdw[H], s_tdb[H];        // decay params (smem)

    const int tid  = threadIdx.x;
    const int lane = tid & 31;
    const int row  = tid >> 1;     // gate row (gate threads)
    const int half = tid & 1;      // K-half: 0 -> floats [0,56), 1 -> [56,112)

    // ---- one-time init: half-row of W_hh in registers, 14 x float4 ----
    float4 w[14];
    if (tid < NGATE) {
        const float* rw = W_hh + row * H + half * 56;
        const int nreal = half ? 52 : 56;     // valid floats in this half
        #pragma unroll
        for (int i = 0; i < 14; i++) {
            float4 v;
            v.x = (4 * i     < nreal) ? rw[4 * i]     : 0.0f;
            v.y = (4 * i + 1 < nreal) ? rw[4 * i + 1] : 0.0f;
            v.z = (4 * i + 2 < nreal) ? rw[4 * i + 2] : 0.0f;
            v.w = (4 * i + 3 < nreal) ? rw[4 * i + 3] : 0.0f;
            w[i] = v;
        }
    } else {
        #pragma unroll
        for (int i = 0; i < 14; i++) w[i] = make_float4(0.f, 0.f, 0.f, 0.f);
    }

    // s_par[kind*4+q][j]: kind0=W_ih[:,0], kind1=W_ih[:,1], kind2=b_ih+b_hh; row r=q*H+j
    for (int k = tid; k < 12 * H; k += NTHR) {
        int j = k % H;
        int f = k / H;
        int q = f & 3;
        int kind = f >> 2;
        int r = q * H + j;
        float v;
        if (kind == 0)      v = W_ih[2 * r];
        else if (kind == 1) v = W_ih[2 * r + 1];
        else                v = b_ih[r] + b_hh[r];
        s_par[f][j] = v;
    }

    if (tid < H) {
        s_c[tid]   = 0.0f;
        s_tdw[tid] = td_w[tid];
        s_tdb[tid] = td_b[tid];
    }
    if (tid < 128) s_hd[tid] = 0.0f;

    float loss = 0.0f, lcomp = 0.0f;   // Kahan loss accumulator (scalar warp lane 0)
    __syncthreads();

    const float4* hvec = (const float4*)(s_hd + half * 56);

    for (int t = 0; t < T_LEN; ++t) {
        const int idx = dir ? (T_LEN - 1 - t) : t;

        // prefetch next step's delta early (LDG hides behind the matvec)
        float dn = 0.0f;
        if (tid < H) {
            int tn = (t + 1 < T_LEN) ? (t + 1) : (T_LEN - 1);
            dn = deltas[tn];
        }

        if (tid < NGATE) {
            // ---- half-row matvec: plain C so ptxas can pipeline the 14 LDS.128 ----
            float a0 = 0.0f, a1 = 0.0f, a2 = 0.0f, a3 = 0.0f;
            #pragma unroll
            for (int i = 0; i < 14; i++) {
                float4 h4 = hvec[i];
                a0 = fmaf(w[i].x, h4.x, a0);
                a1 = fmaf(w[i].y, h4.y, a1);
                a2 = fmaf(w[i].z, h4.z, a2);
                a3 = fmaf(w[i].w, h4.w, a3);
            }
            float s = (a0 + a1) + (a2 + a3);
            float tot = s + __shfl_xor_sync(0xffffffffu, s, 1);
            if (half == 0) s_gates[row] = tot;
        } else {
            // ---- scalar warp: x_h = reg_w . h_decayed + reg_b; x_c; loss; imputation ----
            float r0 = reg_w[lane];
            float r1 = (lane + 32 < H) ? reg_w[lane + 32] : 0.0f;
            float r2 = (lane + 64 < H) ? reg_w[lane + 64] : 0.0f;
            float r3 = (lane + 96 < H) ? reg_w[lane + 96] : 0.0f;
            float p = r0 * s_hd[lane] + r1 * s_hd[lane + 32]
                    + r2 * s_hd[lane + 64] + r3 * s_hd[lane + 96];
            #pragma unroll
            for (int o = 16; o > 0; o >>= 1) p += __shfl_xor_sync(0xffffffffu, p, o);
            if (lane == 0) {
                float xv = values[idx], m = masks[idx];
                float x_h = p + reg_b[0];
                float x_c = m * xv + (1.0f - m) * x_h;
                float term = fabsf(xv - x_h) * m / (m + 1e-5f);
                float y = term - lcomp;
                float ts = loss + y;
                lcomp = (ts - loss) - y;
                loss = ts;
                g_imp[dir][idx] = x_c;     // backward dir: reversed output position == idx
                s_scalar[0] = x_c;
                s_scalar[1] = m;
            }
        }
        __syncthreads();

        // ---- pointwise LSTM cell (threads 0..107 own element j) ----
        if (tid < H) {
            const int j = tid;
            float xc = s_scalar[0], m = s_scalar[1];
            float gi = fmaf(s_par[0][j], xc, fmaf(s_par[4][j], m, s_gates[j]          + s_par[8][j]));
            float gf = fmaf(s_par[1][j], xc, fmaf(s_par[5][j], m, s_gates[H + j]      + s_par[9][j]));
            float gg = fmaf(s_par[2][j], xc, fmaf(s_par[6][j], m, s_gates[2 * H + j]  + s_par[10][j]));
            float go = fmaf(s_par[3][j], xc, fmaf(s_par[7][j], m, s_gates[3 * H + j]  + s_par[11][j]));
            float si = sigmoid_fast(gi);
            float sf = sigmoid_fast(gf);
            float so = sigmoid_fast(go);
            float tg = tanh_fast(gg);
            float c  = sf * s_c[j] + si * tg;
            s_c[j] = c;
            float hh = so * tanh_fast(c);
            // fold next step's temporal decay into the h store (independent chain, hidden)
            float gam = __expf(-fmaxf(fmaf(dn, s_tdw[j], s_tdb[j]), 0.0f));
            s_hd[j] = hh * gam;
        }
        __syncthreads();
    }

    if (tid == NGATE) g_loss[dir] = loss;
}

// ---------------- combine: imputations + per-block |imp_f - imp_b| partial sums ----------------
__global__ void combine_kernel(float* __restrict__ out)
{
    __shared__ float red[256];
    const int i = blockIdx.x * 256 + threadIdx.x;
    float a = g_imp[0][i];
    float b = g_imp[1][i];
    out[1 + i] = 0.5f * (a + b);
    red[threadIdx.x] = fabsf(a - b);
    __syncthreads();
    #pragma unroll
    for (int s = 128; s > 0; s >>= 1) {
        if (threadIdx.x < s) red[threadIdx.x] += red[threadIdx.x + s];
        __syncthreads();
    }
    if (threadIdx.x == 0) g_part[blockIdx.x] = red[0];
}

__global__ void finalize_kernel(float* __restrict__ out)
{
    __shared__ float red[256];
    red[threadIdx.x] = g_part[threadIdx.x];
    __syncthreads();
    #pragma unroll
    for (int s = 128; s > 0; s >>= 1) {
        if (threadIdx.x < s) red[threadIdx.x] += red[threadIdx.x + s];
        __syncthreads();
    }
    if (threadIdx.x == 0) {
        float loss_c = red[0] / (float)T_LEN;
        out[0] = 0.3f * (g_loss[0] + g_loss[1]) + loss_c;
    }
}

// ---------------- launch ----------------
extern "C" void kernel_launch(void* const* d_in, const int* in_sizes, int n_in,
                              void* d_out, int out_size)
{
    (void)in_sizes; (void)n_in; (void)out_size;
    const float* values   = (const float*)d_in[0];
    const float* masks    = (const float*)d_in[1];
    const float* deltas_f = (const float*)d_in[2];
    const float* deltas_b = (const float*)d_in[3];
    const float* f_td_w   = (const float*)d_in[4];
    const float* f_td_b   = (const float*)d_in[5];
    const float* f_reg_w  = (const float*)d_in[6];
    const float* f_reg_b  = (const float*)d_in[7];
    const float* f_W_ih   = (const float*)d_in[8];
    const float* f_W_hh   = (const float*)d_in[9];
    const float* f_b_ih   = (const float*)d_in[10];
    const float* f_b_hh   = (const float*)d_in[11];
    const float* b_td_w   = (const float*)d_in[12];
    const float* b_td_b   = (const float*)d_in[13];
    const float* b_reg_w  = (const float*)d_in[14];
    const float* b_reg_b  = (const float*)d_in[15];
    const float* b_W_ih   = (const float*)d_in[16];
    const float* b_W_hh   = (const float*)d_in[17];
    const float* b_b_ih   = (const float*)d_in[18];
    const float* b_b_hh   = (const float*)d_in[19];
    float* out = (float*)d_out;

    brits_kernel<<<2, NTHR>>>(values, masks, deltas_f, deltas_b,
                              f_td_w, f_td_b, f_reg_w, f_reg_b, f_W_ih, f_W_hh, f_b_ih, f_b_hh,
                              b_td_w, b_td_b, b_reg_w, b_reg_b, b_W_ih, b_W_hh, b_b_ih, b_b_hh);
    combine_kernel<<<T_LEN / 256, 256>>>(out);
    finalize_kernel<<<1, 256>>>(out);
}